// round 6
// baseline (speedup 1.0000x reference)
#include <cuda_runtime.h>
#include <float.h>

// fm [B=4, C=256, H=50, W=50] f32, rois [R=300,5] f32 -> out [R,256,7,7] f32.
#define PH 7
#define PW 7
#define B_ 4
#define C_ 256
#define H_ 50
#define W_ 50
#define HW (H_ * W_)

// channels-last scratch: fmT[b][y][x][c]  (10.24 MB, static device array)
__device__ float g_fmT[B_ * HW * C_];

__device__ __forceinline__ int clampi(int v, int lo, int hi) {
    return min(max(v, lo), hi);
}

// [256, 2500] -> [2500, 256] transpose per batch, 32x32 tiles.
__global__ __launch_bounds__(256) void transpose_kernel(
        const float* __restrict__ in) {
    __shared__ float tile[32][33];
    const int b   = blockIdx.z;
    const int hw0 = blockIdx.x * 32;
    const int c0  = blockIdx.y * 32;
    const int tx  = threadIdx.x;          // 32
    const int ty  = threadIdx.y;          // 8

    #pragma unroll
    for (int j = 0; j < 4; ++j) {
        int cl = ty + j * 8;
        int hw = hw0 + tx;
        if (hw < HW)
            tile[cl][tx] = in[(size_t)(b * C_ + c0 + cl) * HW + hw];
    }
    __syncthreads();
    #pragma unroll
    for (int j = 0; j < 4; ++j) {
        int hwl = ty + j * 8;
        int hw  = hw0 + hwl;
        if (hw < HW)
            g_fmT[(size_t)(b * HW + hw) * C_ + c0 + tx] = tile[tx][hwl];
    }
}

// Block = (ph strip, roi). Thread = channel. Warp of 32 consecutive channels
// reads one 128B line per pixel visit; bin geometry is block-uniform.
__global__ __launch_bounds__(256) void roi_pool_kernel(
        const float* __restrict__ rois, float* __restrict__ out) {
    __shared__ float sm[C_ * PW];          // [c][pw]

    const int ph = blockIdx.x;
    const int r  = blockIdx.y;
    const int c  = threadIdx.x;

    // ---- ROI box (block-uniform; jnp.round == rintf under RN) ----
    const float* rp = rois + r * 5;
    const int b  = (int)__ldg(rp + 4);            // float truncation
    int x0 = clampi((int)rintf(__ldg(rp + 0)), 0, W_ - 1);
    int x1 = clampi((int)rintf(__ldg(rp + 2)), 0, W_ - 1);
    int y0 = clampi((int)rintf(__ldg(rp + 1)), 0, H_ - 1);
    int y1 = clampi((int)rintf(__ldg(rp + 3)), 0, H_ - 1);
    x1 = max(x1, x0 + 1);                  // edges may reach 50; reads <= 49
    y1 = max(y1, y0 + 1);
    const int w = x1 - x0;                 // 1..49
    const int h = y1 - y0;

    const int hs = y0 + (ph * h) / PH;
    const int he = y0 + ((ph + 1) * h + PH - 1) / PH;   // ceil

    int ws[PW], we[PW];
    #pragma unroll
    for (int i = 0; i < PW; ++i) {
        ws[i] = x0 + (i * w) / PW;
        we[i] = x0 + ((i + 1) * w + PW - 1) / PW;
    }

    float m[PW];
    #pragma unroll
    for (int i = 0; i < PW; ++i) m[i] = -FLT_MAX;

    const float* base = g_fmT + (size_t)(b * HW) * C_ + c;

    for (int y = hs; y < he; ++y) {
        const float* row = base + (size_t)(y * W_) * C_;
        #pragma unroll
        for (int pw = 0; pw < PW; ++pw) {
            for (int x = ws[pw]; x < we[pw]; ++x)
                m[pw] = fmaxf(m[pw], __ldg(row + (size_t)x * C_));
        }
    }

    #pragma unroll
    for (int pw = 0; pw < PW; ++pw) sm[c * PW + pw] = m[pw];
    __syncthreads();

    // staged stores: warp writes 32 consecutive (c,pw) slots -> ~2 sectors
    // per 7-float channel run in out[r][c][ph][pw].
    float* ob = out + (size_t)r * (C_ * PH * PW) + ph * PW;
    for (int i = c; i < C_ * PW; i += 256) {
        int cc = i / PW;
        int pp = i - cc * PW;
        ob[cc * (PH * PW) + pp] = sm[i];
    }
}

extern "C" void kernel_launch(void* const* d_in, const int* in_sizes, int n_in,
                              void* d_out, int out_size) {
    const float* fm   = (const float*)d_in[0];
    const float* rois = (const float*)d_in[1];
    float* out = (float*)d_out;

    int R = in_sizes[1] / 5;               // 300

    dim3 tgrid((HW + 31) / 32, C_ / 32, B_);   // 79 x 8 x 4
    transpose_kernel<<<tgrid, dim3(32, 8)>>>(fm);

    dim3 pgrid(PH, R);                     // 7 x 300
    roi_pool_kernel<<<pgrid, 256>>>(rois, out);
}